// round 4
// baseline (speedup 1.0000x reference)
#include <cuda_runtime.h>
#include <math.h>

#define NN 100000
#define EE 3200000
#define FF 13
#define HH 64
#define GG 512
#define BN_EPS 1e-5f
#define NBLK_SCAN 98   // ceil(100000/1024)

// -------- scratch --------
__device__ float g_x16 [NN * 16];
__device__ float g_h1  [NN * 64];
__device__ float g_h2  [NN * 64];
__device__ float g_h3  [NN * 64];
__device__ float g_pool[GG * 192];
__device__ int   g_deg [NN];
__device__ int   g_rowptr[NN + 1];
__device__ int   g_writeptr[NN];
__device__ int   g_part[128];
__device__ int   g_csr [EE];

// -------- f32x2 packed helpers --------
__device__ __forceinline__ unsigned long long pack2(float a, float b) {
    unsigned long long r;
    asm("mov.b64 %0, {%1, %2};" : "=l"(r) : "f"(a), "f"(b));
    return r;
}
__device__ __forceinline__ void unpack2(unsigned long long v, float& a, float& b) {
    asm("mov.b64 {%0, %1}, %2;" : "=f"(a), "=f"(b) : "l"(v));
}
__device__ __forceinline__ void ffma2(unsigned long long& d,
                                      unsigned long long a, unsigned long long b) {
    asm("fma.rn.f32x2 %0, %1, %2, %0;" : "+l"(d) : "l"(a), "l"(b));
}

// -------- init: pad x -> x16, zero degree counters --------
__global__ void init_kernel(const float* __restrict__ x) {
    int i = blockIdx.x * blockDim.x + threadIdx.x;
    if (i < NN * 16) {
        int c = i & 15, n = i >> 4;
        g_x16[i] = (c < FF) ? x[n * FF + c] : 0.0f;
    }
    if (i < NN) g_deg[i] = 0;
}

// -------- CSR build --------
__global__ void count_kernel(const int* __restrict__ dst) {
    int e = blockIdx.x * blockDim.x + threadIdx.x;
    if (e < EE) atomicAdd(&g_deg[dst[e]], 1);
}

__global__ __launch_bounds__(1024) void scan1_kernel() {
    __shared__ int sd[1024];
    int t = threadIdx.x;
    int i = blockIdx.x * 1024 + t;
    int v = (i < NN) ? g_deg[i] : 0;
    sd[t] = v;
    __syncthreads();
#pragma unroll
    for (int off = 1; off < 1024; off <<= 1) {
        int x = (t >= off) ? sd[t - off] : 0;
        __syncthreads();
        sd[t] += x;
        __syncthreads();
    }
    if (i < NN) g_rowptr[i] = sd[t] - v;
    if (t == 1023) g_part[blockIdx.x] = sd[1023];
}

__global__ __launch_bounds__(128) void scan2_kernel() {
    __shared__ int s[128];
    int t = threadIdx.x;
    int v = (t < NBLK_SCAN) ? g_part[t] : 0;
    s[t] = v;
    __syncthreads();
#pragma unroll
    for (int off = 1; off < 128; off <<= 1) {
        int x = (t >= off) ? s[t - off] : 0;
        __syncthreads();
        s[t] += x;
        __syncthreads();
    }
    if (t < NBLK_SCAN) g_part[t] = s[t] - v;
}

__global__ void scan3_kernel() {
    int i = blockIdx.x * blockDim.x + threadIdx.x;
    if (i < NN) {
        int r = g_rowptr[i] + g_part[i >> 10];
        g_rowptr[i] = r;
        g_writeptr[i] = r;
    }
    if (i == 0) g_rowptr[NN] = EE;
}

__global__ void fill_kernel(const int* __restrict__ src, const int* __restrict__ dst) {
    int e = blockIdx.x * blockDim.x + threadIdx.x;
    if (e < EE) {
        int pos = atomicAdd(&g_writeptr[dst[e]], 1);
        g_csr[pos] = src[e];
    }
}

// ============ fused gather + GIN-MLP layer ============
// 128 nodes / 256-thread block.
// Phase A: gather agg = self + sum(neigh) directly into smem.
// Phase B/C: register-blocked f32x2 GEMM x2 with BN+relu fused.
// FIN=64: FINP=66; FIN=16: FINP=18.
template <int FIN, int FINP>
__global__ __launch_bounds__(256)
void fused_layer_kernel(const float* __restrict__ feat,
                        const float* __restrict__ W1, const float* __restrict__ b1,
                        const float* __restrict__ gam, const float* __restrict__ bet,
                        const float* __restrict__ rmean, const float* __restrict__ rvar,
                        const float* __restrict__ W2, const float* __restrict__ b2,
                        int fin_rows,
                        float* __restrict__ h_out) {
    extern __shared__ __align__(16) float smem[];
    float* sW1 = smem;                   // FIN*64
    float* sW2 = sW1 + FIN * 64;         // 4096
    float* sB1 = sW2 + 4096;             // 64
    float* sB2 = sB1 + 64;
    float* sS  = sB2 + 64;
    float* sT  = sS + 64;
    float* sAgg = sT + 64;               // 128*FINP
    float* sMid = sAgg + 128 * FINP;     // 128*65

    int tid = threadIdx.x;
    int wid = tid >> 5, lane = tid & 31;
    int base = blockIdx.x * 128;

    // ---- weights + folded BN ----
    for (int i = tid; i < FIN * 64; i += 256) {
        int k = i >> 6;
        sW1[i] = (k < fin_rows) ? W1[k * 64 + (i & 63)] : 0.0f;
    }
    for (int i = tid; i < 4096; i += 256) sW2[i] = W2[i];
    if (tid < 64) {
        sB1[tid] = b1[tid];
        sB2[tid] = b2[tid];
        float sc = gam[tid] * rsqrtf(rvar[tid] + BN_EPS);
        sS[tid] = sc;
        sT[tid] = bet[tid] - rmean[tid] * sc;
    }

    // ---- Phase A: gather ----
    const float2* fp = reinterpret_cast<const float2*>(feat);
    if (FIN == 64) {
        // warp per node, 32 lanes x float2 = full 64-dim row
        for (int s = 0; s < 16; s++) {
            int node = wid + s * 8;
            int n = base + node;
            float2 acc; acc.x = 0.0f; acc.y = 0.0f;
            if (n < NN) {
                acc = fp[(size_t)n * 32 + lane];
                int rs = __ldg(&g_rowptr[n]);
                int re = __ldg(&g_rowptr[n + 1]);
                int j = rs;
                for (; j + 8 <= re; j += 8) {
                    int i0 = __ldg(&g_csr[j]);
                    int i1 = __ldg(&g_csr[j + 1]);
                    int i2 = __ldg(&g_csr[j + 2]);
                    int i3 = __ldg(&g_csr[j + 3]);
                    int i4 = __ldg(&g_csr[j + 4]);
                    int i5 = __ldg(&g_csr[j + 5]);
                    int i6 = __ldg(&g_csr[j + 6]);
                    int i7 = __ldg(&g_csr[j + 7]);
                    float2 v0 = fp[(size_t)i0 * 32 + lane];
                    float2 v1 = fp[(size_t)i1 * 32 + lane];
                    float2 v2 = fp[(size_t)i2 * 32 + lane];
                    float2 v3 = fp[(size_t)i3 * 32 + lane];
                    float2 v4 = fp[(size_t)i4 * 32 + lane];
                    float2 v5 = fp[(size_t)i5 * 32 + lane];
                    float2 v6 = fp[(size_t)i6 * 32 + lane];
                    float2 v7 = fp[(size_t)i7 * 32 + lane];
                    acc.x += ((v0.x + v1.x) + (v2.x + v3.x)) + ((v4.x + v5.x) + (v6.x + v7.x));
                    acc.y += ((v0.y + v1.y) + (v2.y + v3.y)) + ((v4.y + v5.y) + (v6.y + v7.y));
                }
                for (; j < re; j++) {
                    int nb = __ldg(&g_csr[j]);
                    float2 v = fp[(size_t)nb * 32 + lane];
                    acc.x += v.x; acc.y += v.y;
                }
            }
            *reinterpret_cast<float2*>(&sAgg[node * FINP + lane * 2]) = acc;
        }
    } else {
        // FIN==16: 4 nodes per warp; sub = lane>>3 (node), c2 = lane&7 (col pair)
        int sub = lane >> 3;
        int c2  = lane & 7;
        for (int it = 0; it < 4; it++) {
            int node = wid * 16 + it * 4 + sub;
            int n = base + node;
            float2 acc; acc.x = 0.0f; acc.y = 0.0f;
            int rs = 0, re = 0;
            if (n < NN) {
                acc = fp[(size_t)n * 8 + c2];
                rs = __ldg(&g_rowptr[n]);
                re = __ldg(&g_rowptr[n + 1]);
            }
            for (int j = 0; ; j++) {
                bool act = (rs + j) < re;
                if (!__any_sync(0xffffffffu, act)) break;
                if (act) {
                    int nb = __ldg(&g_csr[rs + j]);
                    float2 v = fp[(size_t)nb * 8 + c2];
                    acc.x += v.x; acc.y += v.y;
                }
            }
            *reinterpret_cast<float2*>(&sAgg[node * FINP + c2 * 2]) = acc;
        }
    }
    __syncthreads();

    // ---- Phase B: agg @ W1, BN, relu -> sMid ----
    int tx = tid & 7;          // cols tx*8..+7
    int ty = tid >> 3;         // nodes ty*4..+3
    int cb = tx * 8;
    int nb4 = ty * 4;

    unsigned long long acc[4][4];
#pragma unroll
    for (int i = 0; i < 4; i++)
#pragma unroll
        for (int p = 0; p < 4; p++) acc[i][p] = 0ull;

#pragma unroll 4
    for (int k = 0; k < FIN; k++) {
        unsigned long long a2[4];
#pragma unroll
        for (int i = 0; i < 4; i++) {
            float a = sAgg[(nb4 + i) * FINP + k];
            a2[i] = pack2(a, a);
        }
        const ulonglong2* wp = reinterpret_cast<const ulonglong2*>(&sW1[k * 64 + cb]);
        ulonglong2 wA = wp[0], wB = wp[1];
#pragma unroll
        for (int i = 0; i < 4; i++) {
            ffma2(acc[i][0], a2[i], wA.x);
            ffma2(acc[i][1], a2[i], wA.y);
            ffma2(acc[i][2], a2[i], wB.x);
            ffma2(acc[i][3], a2[i], wB.y);
        }
    }

#pragma unroll
    for (int i = 0; i < 4; i++) {
#pragma unroll
        for (int p = 0; p < 4; p++) {
            float u, v;
            unpack2(acc[i][p], u, v);
            int j0 = cb + 2 * p, j1 = j0 + 1;
            sMid[(nb4 + i) * 65 + j0] = fmaxf(fmaf(u + sB1[j0], sS[j0], sT[j0]), 0.0f);
            sMid[(nb4 + i) * 65 + j1] = fmaxf(fmaf(v + sB1[j1], sS[j1], sT[j1]), 0.0f);
        }
    }
    __syncthreads();

    // ---- Phase C: mid @ W2, relu -> gmem ----
#pragma unroll
    for (int i = 0; i < 4; i++)
#pragma unroll
        for (int p = 0; p < 4; p++) acc[i][p] = 0ull;

#pragma unroll 4
    for (int k = 0; k < 64; k++) {
        unsigned long long a2[4];
#pragma unroll
        for (int i = 0; i < 4; i++) {
            float a = sMid[(nb4 + i) * 65 + k];
            a2[i] = pack2(a, a);
        }
        const ulonglong2* wp = reinterpret_cast<const ulonglong2*>(&sW2[k * 64 + cb]);
        ulonglong2 wA = wp[0], wB = wp[1];
#pragma unroll
        for (int i = 0; i < 4; i++) {
            ffma2(acc[i][0], a2[i], wA.x);
            ffma2(acc[i][1], a2[i], wA.y);
            ffma2(acc[i][2], a2[i], wB.x);
            ffma2(acc[i][3], a2[i], wB.y);
        }
    }

#pragma unroll
    for (int i = 0; i < 4; i++) {
        int n = base + nb4 + i;
        if (n < NN) {
            float o[8];
#pragma unroll
            for (int p = 0; p < 4; p++) {
                float u, v;
                unpack2(acc[i][p], u, v);
                o[2 * p]     = fmaxf(u + sB2[cb + 2 * p], 0.0f);
                o[2 * p + 1] = fmaxf(v + sB2[cb + 2 * p + 1], 0.0f);
            }
            float4* hp = reinterpret_cast<float4*>(h_out + (size_t)n * 64 + cb);
            float4 v0; v0.x = o[0]; v0.y = o[1]; v0.z = o[2]; v0.w = o[3];
            float4 v1; v1.x = o[4]; v1.y = o[5]; v1.z = o[6]; v1.w = o[7];
            hp[0] = v0; hp[1] = v1;
        }
    }
}

// -------- pooling: batch sorted -> one block per graph --------
__global__ __launch_bounds__(192)
void pool_kernel(const int* __restrict__ batch,
                 const float* __restrict__ h1, const float* __restrict__ h2,
                 const float* __restrict__ h3) {
    __shared__ int sRange[2];
    int g = blockIdx.x;
    if (threadIdx.x == 0) {
        int lo = 0, hi = NN;
        while (lo < hi) { int mid = (lo + hi) >> 1; if (batch[mid] < g) lo = mid + 1; else hi = mid; }
        sRange[0] = lo;
        lo = 0; hi = NN;
        while (lo < hi) { int mid = (lo + hi) >> 1; if (batch[mid] < g + 1) lo = mid + 1; else hi = mid; }
        sRange[1] = lo;
    }
    __syncthreads();
    int j = threadIdx.x;
    const float* src = (j < 64) ? h1 : ((j < 128) ? h2 : h3);
    int col = j & 63;
    int s = sRange[0], e = sRange[1];
    float acc = 0.0f;
    int n = s;
    for (; n + 4 <= e; n += 4) {
        float a0 = src[(size_t)n * 64 + col];
        float a1 = src[(size_t)(n + 1) * 64 + col];
        float a2 = src[(size_t)(n + 2) * 64 + col];
        float a3 = src[(size_t)(n + 3) * 64 + col];
        acc += (a0 + a1) + (a2 + a3);
    }
    for (; n < e; n++) acc += src[(size_t)n * 64 + col];
    g_pool[g * 192 + j] = acc;
}

// -------- head --------
__global__ __launch_bounds__(192)
void head_kernel(const float* __restrict__ fc1W, const float* __restrict__ fc1b,
                 const float* __restrict__ fc2W, const float* __restrict__ fc2b,
                 float* __restrict__ out) {
    __shared__ float sP[192];
    __shared__ float sC0[192];
    __shared__ float sC1[192];
    int g = blockIdx.x, j = threadIdx.x;
    sP[j] = g_pool[g * 192 + j];
    __syncthreads();
    float acc = fc1b[j];
#pragma unroll 4
    for (int k = 0; k < 192; k++) acc = fmaf(sP[k], fc1W[k * 192 + j], acc);
    float h = fmaxf(acc, 0.0f);
    sC0[j] = h * fc2W[j * 2 + 0];
    sC1[j] = h * fc2W[j * 2 + 1];
    __syncthreads();
    if (j == 0) {
        float l0 = fc2b[0], l1 = fc2b[1];
        for (int k = 0; k < 192; k++) { l0 += sC0[k]; l1 += sC1[k]; }
        float m = fmaxf(l0, l1);
        float lse = m + logf(expf(l0 - m) + expf(l1 - m));
        out[g * 2 + 0] = l0 - lse;
        out[g * 2 + 1] = l1 - lse;
    }
}

// ---------------------------------------------------------------------
static float* sym_addr(const void* sym) {
    void* p = nullptr;
    cudaGetSymbolAddress(&p, sym);
    return reinterpret_cast<float*>(p);
}

extern "C" void kernel_launch(void* const* d_in, const int* in_sizes, int n_in,
                              void* d_out, int out_size) {
    const float* x     = (const float*)d_in[0];
    const int*   src   = (const int*)  d_in[1];
    const int*   dst   = (const int*)  d_in[2];
    const int*   batch = (const int*)  d_in[3];

    const float* cp[3][8];
    for (int l = 0; l < 3; l++)
        for (int k = 0; k < 8; k++)
            cp[l][k] = (const float*)d_in[4 + l * 8 + k];
    const float* fc1W = (const float*)d_in[28];
    const float* fc1b = (const float*)d_in[29];
    const float* fc2W = (const float*)d_in[30];
    const float* fc2b = (const float*)d_in[31];
    float* out = (float*)d_out;

    float* x16 = sym_addr(g_x16);
    float* h1  = sym_addr(g_h1);
    float* h2  = sym_addr(g_h2);
    float* h3  = sym_addr(g_h3);

    // smem bytes:
    // FIN64: (4096+4096+256 + 128*66 + 128*65)*4 = (8448 + 8320 + 8448)*4 = 100864
    // FIN16: (1024+4096+256 + 128*18 + 128*65)*4 = (5376 + 2304 + 8320)*4 = 64000
    const int SMEM64 = (4096 + 4096 + 256 + 128 * 66 + 128 * 65) * 4;
    const int SMEM16 = (16 * 64 + 4096 + 256 + 128 * 18 + 128 * 65) * 4;
    cudaFuncSetAttribute(fused_layer_kernel<64, 66>, cudaFuncAttributeMaxDynamicSharedMemorySize, SMEM64);
    cudaFuncSetAttribute(fused_layer_kernel<16, 18>, cudaFuncAttributeMaxDynamicSharedMemorySize, SMEM16);

    // ---- CSR build ----
    init_kernel<<<(NN * 16 + 255) / 256, 256>>>(x);
    count_kernel<<<(EE + 255) / 256, 256>>>(dst);
    scan1_kernel<<<NBLK_SCAN, 1024>>>();
    scan2_kernel<<<1, 128>>>();
    scan3_kernel<<<(NN + 255) / 256, 256>>>();
    fill_kernel<<<(EE + 255) / 256, 256>>>(src, dst);

    int grid = (NN + 127) / 128;

    fused_layer_kernel<16, 18><<<grid, 256, SMEM16>>>(x16,
        cp[0][0], cp[0][1], cp[0][2], cp[0][3], cp[0][4], cp[0][5], cp[0][6], cp[0][7],
        FF, h1);

    fused_layer_kernel<64, 66><<<grid, 256, SMEM64>>>(h1,
        cp[1][0], cp[1][1], cp[1][2], cp[1][3], cp[1][4], cp[1][5], cp[1][6], cp[1][7],
        64, h2);

    fused_layer_kernel<64, 66><<<grid, 256, SMEM64>>>(h2,
        cp[2][0], cp[2][1], cp[2][2], cp[2][3], cp[2][4], cp[2][5], cp[2][6], cp[2][7],
        64, h3);

    pool_kernel<<<GG, 192>>>(batch, h1, h2, h3);
    head_kernel<<<GG, 192>>>(fc1W, fc1b, fc2W, fc2b, out);
}

// round 6
// speedup vs baseline: 1.5055x; 1.5055x over previous
#include <cuda_runtime.h>
#include <cuda_fp16.h>
#include <math.h>

#define NN 100000
#define EE 3200000
#define FF 13
#define HH 64
#define GG 512
#define BN_EPS 1e-5f
#define NBLK_SCAN 98   // ceil(100000/1024)

// -------- scratch --------
__device__ __align__(16) __half2 g_x16h[NN * 8];    // fp16 padded input (8 half2/node)
__device__ __align__(16) __half2 g_hh  [NN * 32];   // fp16 h features (shared h1h/h2h)
__device__ __align__(16) float   g_agg1[NN * 16];
__device__ __align__(16) float   g_agg [NN * 64];
__device__ __align__(16) float   g_pool[GG * 192];
__device__ int g_deg[NN];
__device__ int g_rowptr[NN + 1];
__device__ int g_writeptr[NN];
__device__ int g_part[128];
__device__ int g_csr[EE];

// -------- f32x2 packed helpers --------
__device__ __forceinline__ unsigned long long pack2(float a, float b) {
    unsigned long long r;
    asm("mov.b64 %0, {%1, %2};" : "=l"(r) : "f"(a), "f"(b));
    return r;
}
__device__ __forceinline__ void unpack2(unsigned long long v, float& a, float& b) {
    asm("mov.b64 {%0, %1}, %2;" : "=f"(a), "=f"(b) : "l"(v));
}
__device__ __forceinline__ void ffma2(unsigned long long& d,
                                      unsigned long long a, unsigned long long b) {
    asm("fma.rn.f32x2 %0, %1, %2, %0;" : "+l"(d) : "l"(a), "l"(b));
}
__device__ __forceinline__ void red_add_v4(float* p, float x, float y, float z, float w) {
    asm volatile("red.global.add.v4.f32 [%0], {%1,%2,%3,%4};"
                 :: "l"(p), "f"(x), "f"(y), "f"(z), "f"(w) : "memory");
}

// -------- init: x -> fp16 padded, zero deg + pool --------
__global__ void init_kernel(const float* __restrict__ x) {
    int i = blockIdx.x * blockDim.x + threadIdx.x;
    if (i < NN * 8) {
        int c2 = i & 7, n = i >> 3;
        int c0 = 2 * c2, c1 = c0 + 1;
        float v0 = (c0 < FF) ? x[n * FF + c0] : 0.0f;
        float v1 = (c1 < FF) ? x[n * FF + c1] : 0.0f;
        g_x16h[i] = __floats2half2_rn(v0, v1);
    }
    if (i < NN) g_deg[i] = 0;
    if (i < GG * 192) g_pool[i] = 0.0f;
}

// -------- CSR build --------
__global__ void count_kernel(const int* __restrict__ dst) {
    int e = blockIdx.x * blockDim.x + threadIdx.x;
    if (e < EE) atomicAdd(&g_deg[dst[e]], 1);
}

__global__ __launch_bounds__(1024) void scan1_kernel() {
    __shared__ int sd[1024];
    int t = threadIdx.x;
    int i = blockIdx.x * 1024 + t;
    int v = (i < NN) ? g_deg[i] : 0;
    sd[t] = v;
    __syncthreads();
#pragma unroll
    for (int off = 1; off < 1024; off <<= 1) {
        int x = (t >= off) ? sd[t - off] : 0;
        __syncthreads();
        sd[t] += x;
        __syncthreads();
    }
    if (i < NN) g_rowptr[i] = sd[t] - v;
    if (t == 1023) g_part[blockIdx.x] = sd[1023];
}

__global__ __launch_bounds__(128) void scan2_kernel() {
    __shared__ int s[128];
    int t = threadIdx.x;
    int v = (t < NBLK_SCAN) ? g_part[t] : 0;
    s[t] = v;
    __syncthreads();
#pragma unroll
    for (int off = 1; off < 128; off <<= 1) {
        int x = (t >= off) ? s[t - off] : 0;
        __syncthreads();
        s[t] += x;
        __syncthreads();
    }
    if (t < NBLK_SCAN) g_part[t] = s[t] - v;
}

__global__ void scan3_kernel() {
    int i = blockIdx.x * blockDim.x + threadIdx.x;
    if (i < NN) {
        int r = g_rowptr[i] + g_part[i >> 10];
        g_rowptr[i] = r;
        g_writeptr[i] = r;
    }
    if (i == 0) g_rowptr[NN] = EE;
}

__global__ void fill_kernel(const int* __restrict__ src, const int* __restrict__ dst) {
    int e = blockIdx.x * blockDim.x + threadIdx.x;
    if (e < EE) {
        int pos = atomicAdd(&g_writeptr[dst[e]], 1);
        g_csr[pos] = src[e];
    }
}

// -------- gather-reduce (fp16 features, fp32 accumulate) --------
// LPN lanes per node, each lane owns one half2 (column pair).
template <int LPN>
__global__ __launch_bounds__(256)
void gather_half_kernel(const __half2* __restrict__ feat,
                        float* __restrict__ out) {
    int t = blockIdx.x * blockDim.x + threadIdx.x;
    int n = t / LPN;
    int lane = t - n * LPN;
    if (n >= NN) return;
    int s = g_rowptr[n], e = g_rowptr[n + 1];
    float2 acc = __half22float2(feat[(size_t)n * LPN + lane]);   // self term
    int j = s;
    for (; j + 4 <= e; j += 4) {
        int n0 = __ldg(&g_csr[j]);
        int n1 = __ldg(&g_csr[j + 1]);
        int n2 = __ldg(&g_csr[j + 2]);
        int n3 = __ldg(&g_csr[j + 3]);
        float2 v0 = __half22float2(feat[(size_t)n0 * LPN + lane]);
        float2 v1 = __half22float2(feat[(size_t)n1 * LPN + lane]);
        float2 v2 = __half22float2(feat[(size_t)n2 * LPN + lane]);
        float2 v3 = __half22float2(feat[(size_t)n3 * LPN + lane]);
        acc.x += (v0.x + v1.x) + (v2.x + v3.x);
        acc.y += (v0.y + v1.y) + (v2.y + v3.y);
    }
    for (; j < e; j++) {
        int nb = __ldg(&g_csr[j]);
        float2 v = __half22float2(feat[(size_t)nb * LPN + lane]);
        acc.x += v.x; acc.y += v.y;
    }
    reinterpret_cast<float2*>(out)[(size_t)n * LPN + lane] = acc;
}

// ============ register-blocked fused GIN MLP (Round-3 core) ============
// 128 nodes / 256-thread block; thread = (tx: 8 cols, ty: 4 nodes).
// Epilogue: fp16 feature store (optional) + pooled red.add.v4 into g_pool.
template <int FIN, int FINP>
__global__ __launch_bounds__(256)
void mlp_kernel(const float* __restrict__ in,
                const float* __restrict__ W1, const float* __restrict__ b1,
                const float* __restrict__ gam, const float* __restrict__ bet,
                const float* __restrict__ rmean, const float* __restrict__ rvar,
                const float* __restrict__ W2, const float* __restrict__ b2,
                int fin_rows,
                __half2* __restrict__ hh_out,     // nullable
                const int* __restrict__ batch,
                int pool_off) {
    extern __shared__ __align__(16) float smem[];
    float* sW1 = smem;
    float* sW2 = sW1 + FIN * 64;
    float* sB1 = sW2 + 4096;
    float* sB2 = sB1 + 64;
    float* sS  = sB2 + 64;
    float* sT  = sS + 64;
    float* sMid = sT + 64;                                  // 128*65
    float* sIn = (FIN == 64) ? sMid : (sMid + 128 * 65);    // FIN16: extra 128*FINP

    int tid = threadIdx.x;

    for (int i = tid; i < FIN * 64; i += 256) {
        int k = i >> 6;
        sW1[i] = (k < fin_rows) ? W1[k * 64 + (i & 63)] : 0.0f;
    }
    for (int i = tid; i < 4096; i += 256) sW2[i] = W2[i];
    if (tid < 64) {
        sB1[tid] = b1[tid];
        sB2[tid] = b2[tid];
        float sc = gam[tid] * rsqrtf(rvar[tid] + BN_EPS);
        sS[tid] = sc;
        sT[tid] = bet[tid] - rmean[tid] * sc;
    }

    int base = blockIdx.x * 128;
    for (int i = tid; i < 128 * FIN; i += 256) {
        int r = i / FIN, c = i - r * FIN;
        int n = base + r;
        sIn[r * FINP + c] = (n < NN) ? in[(size_t)n * FIN + c] : 0.0f;
    }
    __syncthreads();

    int tx = tid & 7;
    int ty = tid >> 3;
    int cb = tx * 8;
    int nb = ty * 4;

    unsigned long long acc[4][4];

    // ---- stage 1: in @ W1 ----
#pragma unroll
    for (int i = 0; i < 4; i++)
#pragma unroll
        for (int p = 0; p < 4; p++) acc[i][p] = 0ull;

#pragma unroll 4
    for (int k = 0; k < FIN; k++) {
        unsigned long long a2[4];
#pragma unroll
        for (int i = 0; i < 4; i++) {
            float a = sIn[(nb + i) * FINP + k];
            a2[i] = pack2(a, a);
        }
        const ulonglong2* wp = reinterpret_cast<const ulonglong2*>(&sW1[k * 64 + cb]);
        ulonglong2 wA = wp[0], wB = wp[1];
#pragma unroll
        for (int i = 0; i < 4; i++) {
            ffma2(acc[i][0], a2[i], wA.x);
            ffma2(acc[i][1], a2[i], wA.y);
            ffma2(acc[i][2], a2[i], wB.x);
            ffma2(acc[i][3], a2[i], wB.y);
        }
    }
    __syncthreads();   // sIn reads done before sMid overwrite (FIN==64 alias)

#pragma unroll
    for (int i = 0; i < 4; i++) {
#pragma unroll
        for (int p = 0; p < 4; p++) {
            float u, v;
            unpack2(acc[i][p], u, v);
            int j0 = cb + 2 * p, j1 = j0 + 1;
            sMid[(nb + i) * 65 + j0] = fmaxf(fmaf(u + sB1[j0], sS[j0], sT[j0]), 0.0f);
            sMid[(nb + i) * 65 + j1] = fmaxf(fmaf(v + sB1[j1], sS[j1], sT[j1]), 0.0f);
        }
    }
    __syncthreads();

    // ---- stage 2: mid @ W2 ----
#pragma unroll
    for (int i = 0; i < 4; i++)
#pragma unroll
        for (int p = 0; p < 4; p++) acc[i][p] = 0ull;

#pragma unroll 4
    for (int k = 0; k < 64; k++) {
        unsigned long long a2[4];
#pragma unroll
        for (int i = 0; i < 4; i++) {
            float a = sMid[(nb + i) * 65 + k];
            a2[i] = pack2(a, a);
        }
        const ulonglong2* wp = reinterpret_cast<const ulonglong2*>(&sW2[k * 64 + cb]);
        ulonglong2 wA = wp[0], wB = wp[1];
#pragma unroll
        for (int i = 0; i < 4; i++) {
            ffma2(acc[i][0], a2[i], wA.x);
            ffma2(acc[i][1], a2[i], wA.y);
            ffma2(acc[i][2], a2[i], wB.x);
            ffma2(acc[i][3], a2[i], wB.y);
        }
    }

    // ---- epilogue: relu(+b2), fp16 store, pool atomics ----
#pragma unroll
    for (int i = 0; i < 4; i++) {
        int n = base + nb + i;
        if (n < NN) {
            float o[8];
#pragma unroll
            for (int p = 0; p < 4; p++) {
                float u, v;
                unpack2(acc[i][p], u, v);
                o[2 * p]     = fmaxf(u + sB2[cb + 2 * p], 0.0f);
                o[2 * p + 1] = fmaxf(v + sB2[cb + 2 * p + 1], 0.0f);
            }
            if (hh_out) {
                __half2 hpk[4];
#pragma unroll
                for (int q = 0; q < 4; q++)
                    hpk[q] = __floats2half2_rn(o[2 * q], o[2 * q + 1]);
                *reinterpret_cast<uint4*>(hh_out + (size_t)n * 32 + tx * 4) =
                    *reinterpret_cast<const uint4*>(hpk);
            }
            int b = __ldg(&batch[n]);
            float* pp = &g_pool[b * 192 + pool_off + cb];
            red_add_v4(pp,     o[0], o[1], o[2], o[3]);
            red_add_v4(pp + 4, o[4], o[5], o[6], o[7]);
        }
    }
}

// -------- head --------
__global__ __launch_bounds__(192)
void head_kernel(const float* __restrict__ fc1W, const float* __restrict__ fc1b,
                 const float* __restrict__ fc2W, const float* __restrict__ fc2b,
                 float* __restrict__ out) {
    __shared__ float sP[192];
    __shared__ float sC0[192];
    __shared__ float sC1[192];
    int g = blockIdx.x, j = threadIdx.x;
    sP[j] = g_pool[g * 192 + j];
    __syncthreads();
    float acc = fc1b[j];
#pragma unroll 4
    for (int k = 0; k < 192; k++) acc = fmaf(sP[k], fc1W[k * 192 + j], acc);
    float h = fmaxf(acc, 0.0f);
    sC0[j] = h * fc2W[j * 2 + 0];
    sC1[j] = h * fc2W[j * 2 + 1];
    __syncthreads();
    if (j == 0) {
        float l0 = fc2b[0], l1 = fc2b[1];
        for (int k = 0; k < 192; k++) { l0 += sC0[k]; l1 += sC1[k]; }
        float m = fmaxf(l0, l1);
        float lse = m + logf(expf(l0 - m) + expf(l1 - m));
        out[g * 2 + 0] = l0 - lse;
        out[g * 2 + 1] = l1 - lse;
    }
}

// ---------------------------------------------------------------------
template <typename T>
static T* sym_addr(const void* sym) {
    void* p = nullptr;
    cudaGetSymbolAddress(&p, sym);
    return reinterpret_cast<T*>(p);
}

extern "C" void kernel_launch(void* const* d_in, const int* in_sizes, int n_in,
                              void* d_out, int out_size) {
    const float* x     = (const float*)d_in[0];
    const int*   src   = (const int*)  d_in[1];
    const int*   dst   = (const int*)  d_in[2];
    const int*   batch = (const int*)  d_in[3];

    const float* cp[3][8];
    for (int l = 0; l < 3; l++)
        for (int k = 0; k < 8; k++)
            cp[l][k] = (const float*)d_in[4 + l * 8 + k];
    const float* fc1W = (const float*)d_in[28];
    const float* fc1b = (const float*)d_in[29];
    const float* fc2W = (const float*)d_in[30];
    const float* fc2b = (const float*)d_in[31];
    float* out = (float*)d_out;

    __half2* x16h = sym_addr<__half2>(g_x16h);
    __half2* hh   = sym_addr<__half2>(g_hh);
    float*   agg1 = sym_addr<float>(g_agg1);
    float*   agg  = sym_addr<float>(g_agg);

    const int SMEM64 = (4096 + 4096 + 256 + 128 * 65) * 4;
    const int SMEM16 = (16 * 64 + 4096 + 256 + 128 * 65 + 128 * 17) * 4;
    cudaFuncSetAttribute(mlp_kernel<64, 65>, cudaFuncAttributeMaxDynamicSharedMemorySize, SMEM64);
    cudaFuncSetAttribute(mlp_kernel<16, 17>, cudaFuncAttributeMaxDynamicSharedMemorySize, SMEM16);

    // ---- CSR build + init ----
    init_kernel<<<(NN * 8 + 255) / 256, 256>>>(x);
    count_kernel<<<(EE + 255) / 256, 256>>>(dst);
    scan1_kernel<<<NBLK_SCAN, 1024>>>();
    scan2_kernel<<<1, 128>>>();
    scan3_kernel<<<(NN + 255) / 256, 256>>>();
    fill_kernel<<<(EE + 255) / 256, 256>>>(src, dst);

    int mlp_grid = (NN + 127) / 128;

    // ---- layer 1 ----
    gather_half_kernel<8><<<(NN * 8 + 255) / 256, 256>>>(x16h, agg1);
    mlp_kernel<16, 17><<<mlp_grid, 256, SMEM16>>>(agg1,
        cp[0][0], cp[0][1], cp[0][2], cp[0][3], cp[0][4], cp[0][5], cp[0][6], cp[0][7],
        FF, hh, batch, 0);

    // ---- layer 2 ----
    gather_half_kernel<32><<<(NN * 32 + 255) / 256, 256>>>(hh, agg);
    mlp_kernel<64, 65><<<mlp_grid, 256, SMEM64>>>(agg,
        cp[1][0], cp[1][1], cp[1][2], cp[1][3], cp[1][4], cp[1][5], cp[1][6], cp[1][7],
        64, hh, batch, 64);

    // ---- layer 3 ----
    gather_half_kernel<32><<<(NN * 32 + 255) / 256, 256>>>(hh, agg);
    mlp_kernel<64, 65><<<mlp_grid, 256, SMEM64>>>(agg,
        cp[2][0], cp[2][1], cp[2][2], cp[2][3], cp[2][4], cp[2][5], cp[2][6], cp[2][7],
        64, nullptr, batch, 128);

    // ---- head ----
    head_kernel<<<GG, 192>>>(fc1W, fc1b, fc2W, fc2b, out);
}